// round 3
// baseline (speedup 1.0000x reference)
#include <cuda_runtime.h>

// Shapes (fixed):
//   image: (3, 512, 512) f32
//   x:     (16, 1, 512, 512) f32
//   W:     (9, 3, 3, 3) f32   b: (9,) f32
//   out:   (16, 1, 512, 512) f32
//
// K[c,i,j] = b[c] + sum_{m,u,v} W[c,m,u,v] * image[m, i+u-1, j+v-1]  (zero pad)
// y[n,i,j] = sum_{u,v} x[n, i+u-1, j+v-1] * K[u*3+v, i, j]           (zero pad)

#define HH 512
#define WW 512
#define NB 16
#define PLANE (HH * WW)
#define FULLMASK 0xffffffffu

// Each lane owns 2 horizontally adjacent pixels (cols 2t, 2t+1 within the warp's
// 64-col span). Returns the 4-wide window [col-1, col, col+1, col+2] as r[4].
// Halo columns come from neighbor lanes via shuffle; warp-edge lanes do a
// predicated scalar load (block-uniform haveL/haveR).
__device__ __forceinline__ void load_win(const float* __restrict__ base,
                                         bool rowok, bool haveL, bool haveR,
                                         int lane, float r[4])
{
    float2 v = make_float2(0.f, 0.f);
    if (rowok) v = *(const float2*)base;          // 8B aligned
    float l = __shfl_up_sync(FULLMASK, v.y, 1);
    float h = __shfl_down_sync(FULLMASK, v.x, 1);
    if (lane == 0)  l = (rowok && haveL) ? base[-1] : 0.f;
    if (lane == 31) h = (rowok && haveR) ? base[2]  : 0.f;
    r[0] = l; r[1] = v.x; r[2] = v.y; r[3] = h;
}

__global__ __launch_bounds__(128)
void fused_dynconv2(const float* __restrict__ image,
                    const float* __restrict__ x,
                    const float* __restrict__ Wt,
                    const float* __restrict__ bb,
                    float* __restrict__ y)
{
    // W transposed: Wtr[t*12 + c] = W[c*27 + t]; stride 12 keeps rows 16B aligned
    __shared__ float Wtr[27 * 12];
    __shared__ float bsh[9];

    const int tx  = threadIdx.x;          // lane 0..31
    const int ty  = threadIdx.y;          // 0..3
    const int tid = ty * 32 + tx;

    for (int idx = tid; idx < 243; idx += 128) {
        int c = idx / 27;
        int t = idx % 27;
        Wtr[t * 12 + c] = Wt[idx];
    }
    if (tid < 9) bsh[tid] = bb[tid];
    __syncthreads();   // only barrier

    const int col0 = blockIdx.x * 64 + tx * 2;   // 2 px per thread
    const int i    = blockIdx.y * 4 + ty;

    const bool rok0  = (i > 0);
    const bool rok2  = (i < HH - 1);
    const bool haveL = (blockIdx.x > 0);
    const bool haveR = (blockIdx.x < (WW / 64) - 1);

    // ---------------- K stage: per-pixel 3x3 kernels for 2 pixels ----------------
    float K[18];   // K[c*2 + p]
    #pragma unroll
    for (int c = 0; c < 9; c++) {
        float bc = bsh[c];
        K[c * 2 + 0] = bc;
        K[c * 2 + 1] = bc;
    }

    #pragma unroll
    for (int m = 0; m < 3; m++) {
        float r[3][4];
        const float* base = image + (size_t)(m * HH + i) * WW + col0;
        load_win(base - WW, rok0, haveL, haveR, tx, r[0]);
        load_win(base,      true, haveL, haveR, tx, r[1]);
        load_win(base + WW, rok2, haveL, haveR, tx, r[2]);

        #pragma unroll
        for (int u = 0; u < 3; u++) {
            #pragma unroll
            for (int v = 0; v < 3; v++) {
                const int t = m * 9 + u * 3 + v;
                float4 w0 = *(const float4*)&Wtr[t * 12];
                float4 w1 = *(const float4*)&Wtr[t * 12 + 4];
                float  w8 = Wtr[t * 12 + 8];
                float wv[9] = {w0.x, w0.y, w0.z, w0.w, w1.x, w1.y, w1.z, w1.w, w8};
                #pragma unroll
                for (int c = 0; c < 9; c++) {
                    K[c * 2 + 0] = fmaf(wv[c], r[u][v + 0], K[c * 2 + 0]);
                    K[c * 2 + 1] = fmaf(wv[c], r[u][v + 1], K[c * 2 + 1]);
                }
            }
        }
    }

    // ---------------- apply stage: 16 batch slices ----------------
    const float* xb = x + (size_t)i * WW + col0;
    float*       yb = y + (size_t)i * WW + col0;

    #pragma unroll 2
    for (int n = 0; n < NB; n++) {
        float r[3][4];
        load_win(xb - WW, rok0, haveL, haveR, tx, r[0]);
        load_win(xb,      true, haveL, haveR, tx, r[1]);
        load_win(xb + WW, rok2, haveL, haveR, tx, r[2]);

        float acc0 = 0.f, acc1 = 0.f;
        #pragma unroll
        for (int u = 0; u < 3; u++) {
            #pragma unroll
            for (int v = 0; v < 3; v++) {
                const int c = u * 3 + v;
                acc0 = fmaf(r[u][v + 0], K[c * 2 + 0], acc0);
                acc1 = fmaf(r[u][v + 1], K[c * 2 + 1], acc1);
            }
        }
        float2 o; o.x = acc0; o.y = acc1;
        *(float2*)yb = o;

        xb += PLANE;
        yb += PLANE;
    }
}

extern "C" void kernel_launch(void* const* d_in, const int* in_sizes, int n_in,
                              void* d_out, int out_size)
{
    const float* image = (const float*)d_in[0];   // 3*512*512
    const float* x     = (const float*)d_in[1];   // 16*512*512
    const float* Wt    = (const float*)d_in[2];   // 243
    const float* bb    = (const float*)d_in[3];   // 9
    float* y = (float*)d_out;                     // 16*512*512

    dim3 block(32, 4);            // 128 threads, each owns 2 horizontal pixels
    dim3 grid(WW / 64, HH / 4);   // (8, 128) = 1024 blocks, 4096 warps
    fused_dynconv2<<<grid, block>>>(image, x, Wt, bb, y);
}

// round 4
// speedup vs baseline: 1.1229x; 1.1229x over previous
#include <cuda_runtime.h>

// Shapes (fixed):
//   image: (3, 512, 512) f32
//   x:     (16, 1, 512, 512) f32
//   W:     (9, 3, 3, 3) f32   b: (9,) f32
//   out:   (16, 1, 512, 512) f32
//
// K[c,i,j] = b[c] + sum_{m,u,v} W[c,m,u,v] * image[m, i+u-1, j+v-1]  (zero pad)
// y[n,i,j] = sum_{u,v} x[n, i+u-1, j+v-1] * K[u*3+v, i, j]           (zero pad)

#define HH 512
#define WW 512
#define NB 16
#define PLANE (HH * WW)

// Load a 6-wide row window [col0-1 .. col0+4] with zero padding.
__device__ __forceinline__ void load_row6(const float* __restrict__ base,
                                          bool rowok, bool leftok, bool rightok,
                                          float r[6])
{
    if (rowok) {
        float4 v = *(const float4*)base;          // cols col0..col0+3 (16B aligned)
        r[1] = v.x; r[2] = v.y; r[3] = v.z; r[4] = v.w;
        r[0] = leftok  ? base[-1] : 0.0f;
        r[5] = rightok ? base[4]  : 0.0f;
    } else {
        r[0] = r[1] = r[2] = r[3] = r[4] = r[5] = 0.0f;
    }
}

// Load the full 3x6 stencil window around row i at this thread's 4 pixels.
__device__ __forceinline__ void load_win3(const float* __restrict__ cbase,
                                          bool rok0, bool rok2,
                                          bool lok, bool rtok,
                                          float r[3][6])
{
    load_row6(cbase - WW, rok0, lok, rtok, r[0]);
    load_row6(cbase,      true, lok, rtok, r[1]);
    load_row6(cbase + WW, rok2, lok, rtok, r[2]);
}

// Apply the 4 per-pixel 3x3 kernels to a loaded window.
__device__ __forceinline__ float4 apply_win(const float r[3][6], const float K[36])
{
    float a0 = 0.f, a1 = 0.f, a2 = 0.f, a3 = 0.f;
    #pragma unroll
    for (int u = 0; u < 3; u++) {
        #pragma unroll
        for (int v = 0; v < 3; v++) {
            const int c = u * 3 + v;
            a0 = fmaf(r[u][v + 0], K[c * 4 + 0], a0);
            a1 = fmaf(r[u][v + 1], K[c * 4 + 1], a1);
            a2 = fmaf(r[u][v + 2], K[c * 4 + 2], a2);
            a3 = fmaf(r[u][v + 3], K[c * 4 + 3], a3);
        }
    }
    float4 o; o.x = a0; o.y = a1; o.z = a2; o.w = a3;
    return o;
}

__global__ __launch_bounds__(128)
void fused_dynconv4p(const float* __restrict__ image,
                     const float* __restrict__ x,
                     const float* __restrict__ Wt,
                     const float* __restrict__ bb,
                     float* __restrict__ y)
{
    // W transposed: Wtr[t*12 + c] = W[c*27 + t]; stride 12 keeps rows 16B aligned.
    __shared__ float Wtr[27 * 12];
    __shared__ float bsh[9];

    const int tx  = threadIdx.x;          // 0..31
    const int ty  = threadIdx.y;          // 0..3
    const int tid = ty * 32 + tx;

    for (int idx = tid; idx < 243; idx += 128) {
        int c = idx / 27;
        int t = idx % 27;
        Wtr[t * 12 + c] = Wt[idx];
    }
    if (tid < 9) bsh[tid] = bb[tid];
    __syncthreads();   // only barrier

    const int col0 = (blockIdx.x * 32 + tx) * 4;   // 4 px per thread, 16B aligned
    const int i    = blockIdx.y * 4 + ty;

    const bool rok0 = (i > 0);
    const bool rok2 = (i < HH - 1);
    const bool lok  = (col0 > 0);
    const bool rtok = (col0 < WW - 4);

    const float* xb = x + (size_t)i * WW + col0;
    float*       yb = y + (size_t)i * WW + col0;

    // ---- prefetch x[n=0] window: in flight during the whole K stage ----
    float A[3][6], B[3][6];
    load_win3(xb, rok0, rok2, lok, rtok, A);

    // ---------------- K stage: per-pixel 3x3 kernels for 4 pixels ----------------
    float K[36];   // K[c*4 + p]
    #pragma unroll
    for (int c = 0; c < 9; c++) {
        float bc = bsh[c];
        K[c * 4 + 0] = bc; K[c * 4 + 1] = bc;
        K[c * 4 + 2] = bc; K[c * 4 + 3] = bc;
    }

    #pragma unroll
    for (int m = 0; m < 3; m++) {
        float r[3][6];
        const float* base = image + (size_t)(m * HH + i) * WW + col0;
        load_win3(base, rok0, rok2, lok, rtok, r);

        #pragma unroll
        for (int u = 0; u < 3; u++) {
            #pragma unroll
            for (int v = 0; v < 3; v++) {
                const int t = m * 9 + u * 3 + v;
                float4 w0 = *(const float4*)&Wtr[t * 12];
                float4 w1 = *(const float4*)&Wtr[t * 12 + 4];
                float  w8 = Wtr[t * 12 + 8];
                float wv[9] = {w0.x, w0.y, w0.z, w0.w, w1.x, w1.y, w1.z, w1.w, w8};
                #pragma unroll
                for (int c = 0; c < 9; c++) {
                    #pragma unroll
                    for (int p = 0; p < 4; p++)
                        K[c * 4 + p] = fmaf(wv[c], r[u][v + p], K[c * 4 + p]);
                }
            }
        }
    }

    // ------------- apply stage: double-buffered software pipeline -------------
    // Loads for slice n+1 are issued BEFORE the FMAs of slice n, so the ~250cyc
    // L2 latency is covered by FMA issue. Fully unrolled: all guards fold.
    #pragma unroll
    for (int n = 0; n < NB; n += 2) {
        // prefetch n+1 (NB even -> always valid)
        load_win3(xb + PLANE, rok0, rok2, lok, rtok, B);

        *(float4*)yb = apply_win(A, K);          // compute/store n

        if (n + 2 < NB)                           // prefetch n+2
            load_win3(xb + 2 * PLANE, rok0, rok2, lok, rtok, A);

        *(float4*)(yb + PLANE) = apply_win(B, K); // compute/store n+1

        xb += 2 * PLANE;
        yb += 2 * PLANE;
    }
}

extern "C" void kernel_launch(void* const* d_in, const int* in_sizes, int n_in,
                              void* d_out, int out_size)
{
    const float* image = (const float*)d_in[0];   // 3*512*512
    const float* x     = (const float*)d_in[1];   // 16*512*512
    const float* Wt    = (const float*)d_in[2];   // 243
    const float* bb    = (const float*)d_in[3];   // 9
    float* y = (float*)d_out;                     // 16*512*512

    dim3 block(32, 4);                 // 128 threads, each owns 4 horizontal pixels
    dim3 grid(WW / (32 * 4), HH / 4);  // (4, 128) = 512 blocks
    fused_dynconv4p<<<grid, block>>>(image, x, Wt, bb, y);
}